// round 12
// baseline (speedup 1.0000x reference)
#include <cuda_runtime.h>
#include <cuda_fp16.h>
#include <math.h>

#define IN_DIM 128
#define OUT_DIM 128
#define BATCH 1024
#define BB 16           // batches per warp per block

// out layout (concatenated reference tuple):
//   y_out      : [0, 131072)
//   preacts    : [131072, +16777216)
//   postacts   : next 16777216
//   postspline : next 16777216

__global__ __launch_bounds__(128, 12) void kan_kernel(
    const float* __restrict__ x,
    const float* __restrict__ grid,
    const float* __restrict__ coef,
    const float* __restrict__ scale_base,
    const float* __restrict__ scale_sp,
    const float* __restrict__ mask,
    float* __restrict__ out)
{
    const int lane = threadIdx.x & 31;
    const int warp = threadIdx.x >> 5;          // each warp owns its own b stream
    const int j    = blockIdx.x;                // output-dim index
    const int sb   = j * IN_DIM;

    // per-interval cubic polynomial table, fp16-packed:
    // ctabh[i][qc] = uint2{ half2(A,B), half2(C,D) } for interval qc-1.
    // qc=0 / qc=12 are zero polys. Row stride 13*uint2 = 26 words: with
    // i = lane + 32r the 16-lane LDS.64 phase tiles all 32 banks.
    __shared__ uint2 ctabh[128][13];

    {
        // one thread per element row
        const int i = threadIdx.x;
        const float4 c0 = *(const float4*)&coef[(size_t)(sb + i) * 8 + 0];
        const float4 c1 = *(const float4*)&coef[(size_t)(sb + i) * 8 + 4];
        float cm[8] = {c0.x, c0.y, c0.z, c0.w, c1.x, c1.y, c1.z, c1.w};

        ctabh[i][0]  = make_uint2(0u, 0u);
        ctabh[i][12] = make_uint2(0u, 0u);
        #pragma unroll
        for (int q = 0; q < 11; q++) {
            const int m0 = q - 3;
            float k0 = (m0 + 0 >= 0 && m0 + 0 <= 7) ? cm[m0 + 0] : 0.0f;
            float k1 = (m0 + 1 >= 0 && m0 + 1 <= 7) ? cm[m0 + 1] : 0.0f;
            float k2 = (m0 + 2 >= 0 && m0 + 2 <= 7) ? cm[m0 + 2] : 0.0f;
            float k3 = (m0 + 3 >= 0 && m0 + 3 <= 7) ? cm[m0 + 3] : 0.0f;
            float A  = (k0 + 4.0f * k1 + k2) * (1.0f / 6.0f);
            float Bc = (k2 - k0) * 0.5f;
            float Cc = (k0 - 2.0f * k1 + k2) * 0.5f;
            float D  = (k3 - k0) * (1.0f / 6.0f) + (k1 - k2) * 0.5f;
            __half2 ab = __floats2half2_rn(A, Bc);
            __half2 cd = __floats2half2_rn(Cc, D);
            ctabh[i][q + 1] = make_uint2(*(unsigned*)&ab, *(unsigned*)&cd);
        }
    }

    // per-element loop-invariant setup; element r of this thread is i = lane + 32r
    float poff[4], invh[4], msb[4], mssp[4];
    #pragma unroll
    for (int r = 0; r < 4; r++) {
        const int s = sb + lane + 32 * r;
        float g0 = grid[s * 6 + 0];
        float g5 = grid[s * 6 + 5];
        float h  = (g5 - g0) * 0.2f;
        float e0 = g0 - h; e0 -= h; e0 -= h;    // match reference's sequential extension
        float ih = 1.0f / h;
        invh[r] = ih;
        poff[r] = -e0 * ih;                      // pos = t*ih + poff
        float mv = mask[s];
        msb[r]  = mv * scale_base[s];
        mssp[r] = mv * scale_sp[s];
    }

    __syncthreads();   // ctabh ready; the ONLY block barrier

    float* y_out      = out;
    float* preacts    = out + 131072;
    float* postacts   = preacts + 16777216;
    float* postspline = postacts + 16777216;

    const int b_start = blockIdx.y * (4 * BB) + warp * BB;

    float tn[4];
    #pragma unroll
    for (int r = 0; r < 4; r++)
        tn[r] = x[b_start * IN_DIM + lane + 32 * r];   // prefetch

    #pragma unroll 2
    for (int bb = 0; bb < BB; bb++) {
        const int b = b_start + bb;

        float t[4];
        #pragma unroll
        for (int r = 0; r < 4; r++) t[r] = tn[r];
        if (bb + 1 < BB) {
            #pragma unroll
            for (int r = 0; r < 4; r++)
                tn[r] = x[(b + 1) * IN_DIM + lane + 32 * r];
        }

        float y[4], spl[4];
        #pragma unroll
        for (int r = 0; r < 4; r++) {
            const int i = lane + 32 * r;

            // silu via MUFU (fast exp + fast divide)
            float base = __fdividef(t[r], 1.0f + __expf(-t[r]));

            // spline via per-interval cubic (Horner), fp16 table
            float pos = fmaf(t[r], invh[r], poff[r]);
            float qf  = floorf(pos);
            float u   = pos - qf;
            int   qc  = min(max((int)qf, -1), 11) + 1;   // 0..12

            const uint2 e = ctabh[i][qc];
            float2 ab = __half22float2(*(const __half2*)&e.x);
            float2 cd = __half22float2(*(const __half2*)&e.y);
            float sp = fmaf(fmaf(fmaf(cd.y, u, cd.x), u, ab.y), u, ab.x);

            spl[r] = sp;
            y[r]   = fmaf(msb[r], base, mssp[r] * sp);
        }

        const size_t rowbase = ((size_t)b * OUT_DIM + j) * IN_DIM + lane;
        #pragma unroll
        for (int r = 0; r < 4; r++) {
            __stcs(&preacts[rowbase + 32 * r],    t[r]);
            __stcs(&postacts[rowbase + 32 * r],   y[r]);
            __stcs(&postspline[rowbase + 32 * r], spl[r]);
        }

        // y_out[b, j] = sum over all 128 i — pure warp reduction
        float v = (y[0] + y[1]) + (y[2] + y[3]);
        #pragma unroll
        for (int o = 16; o; o >>= 1) v += __shfl_xor_sync(0xffffffffu, v, o);
        if (lane == 0) y_out[(size_t)b * OUT_DIM + j] = v;
    }
}

extern "C" void kernel_launch(void* const* d_in, const int* in_sizes, int n_in,
                              void* d_out, int out_size) {
    const float* x          = (const float*)d_in[0];
    const float* grid       = (const float*)d_in[1];
    const float* coef       = (const float*)d_in[2];
    const float* scale_base = (const float*)d_in[3];
    const float* scale_sp   = (const float*)d_in[4];
    const float* mask       = (const float*)d_in[5];
    float* out = (float*)d_out;

    dim3 gridDim(OUT_DIM, BATCH / (4 * BB));   // (128, 16) = 2048 blocks
    dim3 blockDim(128);
    kan_kernel<<<gridDim, blockDim>>>(x, grid, coef, scale_base, scale_sp, mask, out);
}

// round 13
// speedup vs baseline: 1.2895x; 1.2895x over previous
#include <cuda_runtime.h>
#include <cuda_fp16.h>
#include <math.h>

#define IN_DIM 128
#define OUT_DIM 128
#define BATCH 1024
#define BB 16           // batches per warp per block

// out layout (concatenated reference tuple):
//   y_out      : [0, 131072)
//   preacts    : [131072, +16777216)
//   postacts   : next 16777216
//   postspline : next 16777216

__global__ __launch_bounds__(128, 10) void kan_kernel(
    const float* __restrict__ x,
    const float* __restrict__ grid,
    const float* __restrict__ coef,
    const float* __restrict__ scale_base,
    const float* __restrict__ scale_sp,
    const float* __restrict__ mask,
    float* __restrict__ out)
{
    const int lane = threadIdx.x & 31;
    const int warp = threadIdx.x >> 5;          // each warp owns its own b stream
    const int j    = blockIdx.x;                // output-dim index
    const int sb   = j * IN_DIM;

    // per-interval cubic polynomial table, fp16-packed:
    // ctabh[i][qc] = uint2{ half2(A,B), half2(C,D) } for interval qc-1.
    // qc=0 / qc=12 are zero polys. Row stride 13*uint2 = 26 words: with
    // i = lane + 32r the 16-lane LDS.64 phase tiles all 32 banks.
    __shared__ uint2 ctabh[128][13];

    {
        // one thread per element row
        const int i = threadIdx.x;
        const float4 c0 = *(const float4*)&coef[(size_t)(sb + i) * 8 + 0];
        const float4 c1 = *(const float4*)&coef[(size_t)(sb + i) * 8 + 4];
        float cm[8] = {c0.x, c0.y, c0.z, c0.w, c1.x, c1.y, c1.z, c1.w};

        ctabh[i][0]  = make_uint2(0u, 0u);
        ctabh[i][12] = make_uint2(0u, 0u);
        #pragma unroll
        for (int q = 0; q < 11; q++) {
            const int m0 = q - 3;
            float k0 = (m0 + 0 >= 0 && m0 + 0 <= 7) ? cm[m0 + 0] : 0.0f;
            float k1 = (m0 + 1 >= 0 && m0 + 1 <= 7) ? cm[m0 + 1] : 0.0f;
            float k2 = (m0 + 2 >= 0 && m0 + 2 <= 7) ? cm[m0 + 2] : 0.0f;
            float k3 = (m0 + 3 >= 0 && m0 + 3 <= 7) ? cm[m0 + 3] : 0.0f;
            float A  = (k0 + 4.0f * k1 + k2) * (1.0f / 6.0f);
            float Bc = (k2 - k0) * 0.5f;
            float Cc = (k0 - 2.0f * k1 + k2) * 0.5f;
            float D  = (k3 - k0) * (1.0f / 6.0f) + (k1 - k2) * 0.5f;
            __half2 ab = __floats2half2_rn(A, Bc);
            __half2 cd = __floats2half2_rn(Cc, D);
            ctabh[i][q + 1] = make_uint2(*(unsigned*)&ab, *(unsigned*)&cd);
        }
    }

    // per-element loop-invariant setup; element r of this thread is i = lane + 32r
    float poff[4], invh[4], msb[4], mssp[4];
    #pragma unroll
    for (int r = 0; r < 4; r++) {
        const int s = sb + lane + 32 * r;
        float g0 = grid[s * 6 + 0];
        float g5 = grid[s * 6 + 5];
        float h  = (g5 - g0) * 0.2f;
        float e0 = g0 - h; e0 -= h; e0 -= h;    // match reference's sequential extension
        float ih = 1.0f / h;
        invh[r] = ih;
        poff[r] = -e0 * ih;                      // pos = t*ih + poff
        float mv = mask[s];
        msb[r]  = mv * scale_base[s];
        mssp[r] = mv * scale_sp[s];
    }

    __syncthreads();   // ctabh ready; the ONLY block barrier

    float* y_out      = out;
    float* preacts    = out + 131072;
    float* postacts   = preacts + 16777216;
    float* postspline = postacts + 16777216;

    const int b_start = blockIdx.y * (4 * BB) + warp * BB;

    float tn[4];
    #pragma unroll
    for (int r = 0; r < 4; r++)
        tn[r] = x[b_start * IN_DIM + lane + 32 * r];   // prefetch

    #pragma unroll 2
    for (int bb = 0; bb < BB; bb++) {
        const int b = b_start + bb;

        float t[4];
        #pragma unroll
        for (int r = 0; r < 4; r++) t[r] = tn[r];
        if (bb + 1 < BB) {
            #pragma unroll
            for (int r = 0; r < 4; r++)
                tn[r] = x[(b + 1) * IN_DIM + lane + 32 * r];
        }

        float y[4], spl[4];
        #pragma unroll
        for (int r = 0; r < 4; r++) {
            const int i = lane + 32 * r;

            // silu via MUFU (fast exp + fast divide)
            float base = __fdividef(t[r], 1.0f + __expf(-t[r]));

            // spline via per-interval cubic (Horner), fp16 table
            float pos = fmaf(t[r], invh[r], poff[r]);
            float qf  = floorf(pos);
            float u   = pos - qf;
            int   qc  = min(max((int)qf, -1), 11) + 1;   // 0..12

            const uint2 e = ctabh[i][qc];
            float2 ab = __half22float2(*(const __half2*)&e.x);
            float2 cd = __half22float2(*(const __half2*)&e.y);
            float sp = fmaf(fmaf(fmaf(cd.y, u, cd.x), u, ab.y), u, ab.x);

            spl[r] = sp;
            y[r]   = fmaf(msb[r], base, mssp[r] * sp);
        }

        const size_t rowbase = ((size_t)b * OUT_DIM + j) * IN_DIM + lane;
        #pragma unroll
        for (int r = 0; r < 4; r++) {
            __stcs(&preacts[rowbase + 32 * r],    t[r]);
            __stcs(&postacts[rowbase + 32 * r],   y[r]);
            __stcs(&postspline[rowbase + 32 * r], spl[r]);
        }

        // y_out[b, j] = sum over all 128 i — pure warp reduction
        float v = (y[0] + y[1]) + (y[2] + y[3]);
        #pragma unroll
        for (int o = 16; o; o >>= 1) v += __shfl_xor_sync(0xffffffffu, v, o);
        if (lane == 0) y_out[(size_t)b * OUT_DIM + j] = v;
    }
}

extern "C" void kernel_launch(void* const* d_in, const int* in_sizes, int n_in,
                              void* d_out, int out_size) {
    const float* x          = (const float*)d_in[0];
    const float* grid       = (const float*)d_in[1];
    const float* coef       = (const float*)d_in[2];
    const float* scale_base = (const float*)d_in[3];
    const float* scale_sp   = (const float*)d_in[4];
    const float* mask       = (const float*)d_in[5];
    float* out = (float*)d_out;

    dim3 gridDim(OUT_DIM, BATCH / (4 * BB));   // (128, 16) = 2048 blocks
    dim3 blockDim(128);
    kan_kernel<<<gridDim, blockDim>>>(x, grid, coef, scale_base, scale_sp, mask, out);
}

// round 14
// speedup vs baseline: 1.4437x; 1.1196x over previous
#include <cuda_runtime.h>
#include <cuda_fp16.h>
#include <math.h>

#define IN_DIM 128
#define OUT_DIM 128
#define BATCH 1024
#define BB 8            // batches per warp per block

// out layout (concatenated reference tuple):
//   y_out      : [0, 131072)
//   preacts    : [131072, +16777216)
//   postacts   : next 16777216
//   postspline : next 16777216

__global__ __launch_bounds__(128) void kan_kernel(
    const float* __restrict__ x,
    const float* __restrict__ grid,
    const float* __restrict__ coef,
    const float* __restrict__ scale_base,
    const float* __restrict__ scale_sp,
    const float* __restrict__ mask,
    float* __restrict__ out)
{
    const int lane = threadIdx.x & 31;
    const int warp = threadIdx.x >> 5;          // each warp owns its own b stream
    const int j    = blockIdx.x;                // output-dim index
    const int sb   = j * IN_DIM;

    // per-interval cubic polynomial table, fp16-packed:
    // ctabh[i][qc] = uint2{ half2(A,B), half2(C,D) } for interval qc-1.
    // qc=0 / qc=12 are zero polys. Row stride 13*uint2 = 26 words: with
    // i = lane + 32r the 16-lane LDS.64 phase tiles all 32 banks.
    __shared__ uint2 ctabh[128][13];

    {
        // one thread per element row
        const int i = threadIdx.x;
        const float4 c0 = *(const float4*)&coef[(size_t)(sb + i) * 8 + 0];
        const float4 c1 = *(const float4*)&coef[(size_t)(sb + i) * 8 + 4];
        float cm[8] = {c0.x, c0.y, c0.z, c0.w, c1.x, c1.y, c1.z, c1.w};

        ctabh[i][0]  = make_uint2(0u, 0u);
        ctabh[i][12] = make_uint2(0u, 0u);
        #pragma unroll
        for (int q = 0; q < 11; q++) {
            const int m0 = q - 3;
            float k0 = (m0 + 0 >= 0 && m0 + 0 <= 7) ? cm[m0 + 0] : 0.0f;
            float k1 = (m0 + 1 >= 0 && m0 + 1 <= 7) ? cm[m0 + 1] : 0.0f;
            float k2 = (m0 + 2 >= 0 && m0 + 2 <= 7) ? cm[m0 + 2] : 0.0f;
            float k3 = (m0 + 3 >= 0 && m0 + 3 <= 7) ? cm[m0 + 3] : 0.0f;
            float A  = (k0 + 4.0f * k1 + k2) * (1.0f / 6.0f);
            float Bc = (k2 - k0) * 0.5f;
            float Cc = (k0 - 2.0f * k1 + k2) * 0.5f;
            float D  = (k3 - k0) * (1.0f / 6.0f) + (k1 - k2) * 0.5f;
            __half2 ab = __floats2half2_rn(A, Bc);
            __half2 cd = __floats2half2_rn(Cc, D);
            ctabh[i][q + 1] = make_uint2(*(unsigned*)&ab, *(unsigned*)&cd);
        }
    }

    // per-element loop-invariant setup; element r of this thread is i = lane + 32r
    float poff[4], invh[4], msb[4], mssp[4];
    #pragma unroll
    for (int r = 0; r < 4; r++) {
        const int s = sb + lane + 32 * r;
        float g0 = grid[s * 6 + 0];
        float g5 = grid[s * 6 + 5];
        float h  = (g5 - g0) * 0.2f;
        float e0 = g0 - h; e0 -= h; e0 -= h;    // match reference's sequential extension
        float ih = 1.0f / h;
        invh[r] = ih;
        poff[r] = -e0 * ih;                      // pos = t*ih + poff
        float mv = mask[s];
        msb[r]  = mv * scale_base[s];
        mssp[r] = mv * scale_sp[s];
    }

    __syncthreads();   // ctabh ready; the ONLY block barrier

    const int b_start = blockIdx.y * (4 * BB) + warp * BB;

    // hoisted, pointer-bumped addressing: stores become STG [ptr + imm]
    const size_t obase = ((size_t)b_start * OUT_DIM + j) * IN_DIM + lane;
    const float* xp  = x + (size_t)b_start * IN_DIM + lane;
    float* yo  = out + (size_t)b_start * OUT_DIM + j;
    float* pre = out + 131072            + obase;
    float* pac = out + 131072 + 16777216 + obase;
    float* psp = out + 131072 + 33554432 + obase;
    const int OSTRIDE = OUT_DIM * IN_DIM;   // 16384 floats per batch step

    float tn[4];
    #pragma unroll
    for (int r = 0; r < 4; r++) tn[r] = xp[32 * r];   // prefetch
    xp += IN_DIM;

    #pragma unroll 2
    for (int bb = 0; bb < BB; bb++) {
        float t[4];
        #pragma unroll
        for (int r = 0; r < 4; r++) t[r] = tn[r];
        if (bb + 1 < BB) {
            #pragma unroll
            for (int r = 0; r < 4; r++) tn[r] = xp[32 * r];
            xp += IN_DIM;
        }

        float y[4], spl[4];
        #pragma unroll
        for (int r = 0; r < 4; r++) {
            const int i = lane + 32 * r;

            // silu via MUFU (fast exp + fast divide)
            float base = __fdividef(t[r], 1.0f + __expf(-t[r]));

            // spline via per-interval cubic (Horner), fp16 table
            float pos = fmaf(t[r], invh[r], poff[r]);
            float qf  = floorf(pos);
            float u   = pos - qf;
            int   qc  = min(max((int)qf, -1), 11) + 1;   // 0..12

            const uint2 e = ctabh[i][qc];
            float2 ab = __half22float2(*(const __half2*)&e.x);
            float2 cd = __half22float2(*(const __half2*)&e.y);
            float sp = fmaf(fmaf(fmaf(cd.y, u, cd.x), u, ab.y), u, ab.x);

            spl[r] = sp;
            y[r]   = fmaf(msb[r], base, mssp[r] * sp);
        }

        #pragma unroll
        for (int r = 0; r < 4; r++) {
            __stcs(pre + 32 * r, t[r]);
            __stcs(pac + 32 * r, y[r]);
            __stcs(psp + 32 * r, spl[r]);
        }
        pre += OSTRIDE; pac += OSTRIDE; psp += OSTRIDE;

        // y_out[b, j] = sum over all 128 i — pure warp reduction
        float v = (y[0] + y[1]) + (y[2] + y[3]);
        #pragma unroll
        for (int o = 16; o; o >>= 1) v += __shfl_xor_sync(0xffffffffu, v, o);
        if (lane == 0) *yo = v;
        yo += OUT_DIM;
    }
}

extern "C" void kernel_launch(void* const* d_in, const int* in_sizes, int n_in,
                              void* d_out, int out_size) {
    const float* x          = (const float*)d_in[0];
    const float* grid       = (const float*)d_in[1];
    const float* coef       = (const float*)d_in[2];
    const float* scale_base = (const float*)d_in[3];
    const float* scale_sp   = (const float*)d_in[4];
    const float* mask       = (const float*)d_in[5];
    float* out = (float*)d_out;

    dim3 gridDim(OUT_DIM, BATCH / (4 * BB));   // (128, 32) = 4096 blocks
    dim3 blockDim(128);
    kan_kernel<<<gridDim, blockDim>>>(x, grid, coef, scale_base, scale_sp, mask, out);
}

// round 15
// speedup vs baseline: 1.5050x; 1.0425x over previous
#include <cuda_runtime.h>
#include <cuda_fp16.h>
#include <math.h>

#define IN_DIM 128
#define OUT_DIM 128
#define BATCH 1024
#define BB 8            // batches per warp per block

// out layout (concatenated reference tuple):
//   y_out      : [0, 131072)
//   preacts    : [131072, +16777216)
//   postacts   : next 16777216
//   postspline : next 16777216

__global__ __launch_bounds__(128) void kan_kernel(
    const float* __restrict__ x,
    const float* __restrict__ grid,
    const float* __restrict__ coef,
    const float* __restrict__ scale_base,
    const float* __restrict__ scale_sp,
    const float* __restrict__ mask,
    float* __restrict__ out)
{
    const int lane = threadIdx.x & 31;
    const int warp = threadIdx.x >> 5;          // each warp owns its own b stream
    const int j    = blockIdx.x;                // output-dim index
    const int sb   = j * IN_DIM;

    // per-interval cubic polynomial table, fp16-packed, TRANSPOSED:
    // ctabh[qc][i] = uint2{ half2(A,B), half2(C,D) } for element i, interval qc-1.
    // Word offset = qc*256 + 2i and 256 % 32 == 0, so the smem bank depends on
    // i ONLY: a 16-lane LDS.64 phase (i = lane + 32r) hits bank pairs (2l,2l+1)
    // for l = 0..15 -> all 32 banks exactly once, independent of per-lane qc.
    // Data-dependent conflicts are structurally impossible.
    __shared__ uint2 ctabh[13][128];

    {
        // one thread per element row
        const int i = threadIdx.x;
        const float4 c0 = *(const float4*)&coef[(size_t)(sb + i) * 8 + 0];
        const float4 c1 = *(const float4*)&coef[(size_t)(sb + i) * 8 + 4];
        float cm[8] = {c0.x, c0.y, c0.z, c0.w, c1.x, c1.y, c1.z, c1.w};

        ctabh[0][i]  = make_uint2(0u, 0u);
        ctabh[12][i] = make_uint2(0u, 0u);
        #pragma unroll
        for (int q = 0; q < 11; q++) {
            const int m0 = q - 3;
            float k0 = (m0 + 0 >= 0 && m0 + 0 <= 7) ? cm[m0 + 0] : 0.0f;
            float k1 = (m0 + 1 >= 0 && m0 + 1 <= 7) ? cm[m0 + 1] : 0.0f;
            float k2 = (m0 + 2 >= 0 && m0 + 2 <= 7) ? cm[m0 + 2] : 0.0f;
            float k3 = (m0 + 3 >= 0 && m0 + 3 <= 7) ? cm[m0 + 3] : 0.0f;
            float A  = (k0 + 4.0f * k1 + k2) * (1.0f / 6.0f);
            float Bc = (k2 - k0) * 0.5f;
            float Cc = (k0 - 2.0f * k1 + k2) * 0.5f;
            float D  = (k3 - k0) * (1.0f / 6.0f) + (k1 - k2) * 0.5f;
            __half2 ab = __floats2half2_rn(A, Bc);
            __half2 cd = __floats2half2_rn(Cc, D);
            ctabh[q + 1][i] = make_uint2(*(unsigned*)&ab, *(unsigned*)&cd);
        }
    }

    // per-element loop-invariant setup; element r of this thread is i = lane + 32r
    float poff[4], invh[4], msb[4], mssp[4];
    #pragma unroll
    for (int r = 0; r < 4; r++) {
        const int s = sb + lane + 32 * r;
        float g0 = grid[s * 6 + 0];
        float g5 = grid[s * 6 + 5];
        float h  = (g5 - g0) * 0.2f;
        float e0 = g0 - h; e0 -= h; e0 -= h;    // match reference's sequential extension
        float ih = 1.0f / h;
        invh[r] = ih;
        poff[r] = -e0 * ih;                      // pos = t*ih + poff
        float mv = mask[s];
        msb[r]  = mv * scale_base[s];
        mssp[r] = mv * scale_sp[s];
    }

    __syncthreads();   // ctabh ready; the ONLY block barrier

    const int b_start = blockIdx.y * (4 * BB) + warp * BB;

    // hoisted, pointer-bumped addressing: stores become STG [ptr + imm]
    const size_t obase = ((size_t)b_start * OUT_DIM + j) * IN_DIM + lane;
    const float* xp  = x + (size_t)b_start * IN_DIM + lane;
    float* yo  = out + (size_t)b_start * OUT_DIM + j;
    float* pre = out + 131072            + obase;
    float* pac = out + 131072 + 16777216 + obase;
    float* psp = out + 131072 + 33554432 + obase;
    const int OSTRIDE = OUT_DIM * IN_DIM;   // 16384 floats per batch step

    float tn[4];
    #pragma unroll
    for (int r = 0; r < 4; r++) tn[r] = xp[32 * r];   // prefetch
    xp += IN_DIM;

    #pragma unroll 2
    for (int bb = 0; bb < BB; bb++) {
        float t[4];
        #pragma unroll
        for (int r = 0; r < 4; r++) t[r] = tn[r];
        if (bb + 1 < BB) {
            #pragma unroll
            for (int r = 0; r < 4; r++) tn[r] = xp[32 * r];
            xp += IN_DIM;
        }

        float y[4], spl[4];
        #pragma unroll
        for (int r = 0; r < 4; r++) {
            const int i = lane + 32 * r;

            // silu via MUFU (fast exp + fast divide)
            float base = __fdividef(t[r], 1.0f + __expf(-t[r]));

            // spline via per-interval cubic (Horner), fp16 table
            float pos = fmaf(t[r], invh[r], poff[r]);
            float qf  = floorf(pos);
            float u   = pos - qf;
            int   qc  = min(max((int)qf, -1), 11) + 1;   // 0..12

            const uint2 e = ctabh[qc][i];
            float2 ab = __half22float2(*(const __half2*)&e.x);
            float2 cd = __half22float2(*(const __half2*)&e.y);
            float sp = fmaf(fmaf(fmaf(cd.y, u, cd.x), u, ab.y), u, ab.x);

            spl[r] = sp;
            y[r]   = fmaf(msb[r], base, mssp[r] * sp);
        }

        #pragma unroll
        for (int r = 0; r < 4; r++) {
            __stcs(pre + 32 * r, t[r]);
            __stcs(pac + 32 * r, y[r]);
            __stcs(psp + 32 * r, spl[r]);
        }
        pre += OSTRIDE; pac += OSTRIDE; psp += OSTRIDE;

        // y_out[b, j] = sum over all 128 i — pure warp reduction
        float v = (y[0] + y[1]) + (y[2] + y[3]);
        #pragma unroll
        for (int o = 16; o; o >>= 1) v += __shfl_xor_sync(0xffffffffu, v, o);
        if (lane == 0) *yo = v;
        yo += OUT_DIM;
    }
}

extern "C" void kernel_launch(void* const* d_in, const int* in_sizes, int n_in,
                              void* d_out, int out_size) {
    const float* x          = (const float*)d_in[0];
    const float* grid       = (const float*)d_in[1];
    const float* coef       = (const float*)d_in[2];
    const float* scale_base = (const float*)d_in[3];
    const float* scale_sp   = (const float*)d_in[4];
    const float* mask       = (const float*)d_in[5];
    float* out = (float*)d_out;

    dim3 gridDim(OUT_DIM, BATCH / (4 * BB));   // (128, 32) = 4096 blocks
    dim3 blockDim(128);
    kan_kernel<<<gridDim, blockDim>>>(x, grid, coef, scale_base, scale_sp, mask, out);
}

// round 16
// speedup vs baseline: 1.5104x; 1.0036x over previous
#include <cuda_runtime.h>
#include <cuda_fp16.h>
#include <math.h>

#define IN_DIM 128
#define OUT_DIM 128
#define BATCH 1024
#define BB 8            // batches per warp per block

// out layout (concatenated reference tuple):
//   y_out      : [0, 131072)
//   preacts    : [131072, +16777216)
//   postacts   : next 16777216
//   postspline : next 16777216

__global__ __launch_bounds__(128) void kan_kernel(
    const float* __restrict__ x,
    const float* __restrict__ grid,
    const float* __restrict__ coef,
    const float* __restrict__ scale_base,
    const float* __restrict__ scale_sp,
    const float* __restrict__ mask,
    float* __restrict__ out)
{
    const int lane = threadIdx.x & 31;
    const int warp = threadIdx.x >> 5;          // each warp owns its own b stream
    const int j    = blockIdx.x;                // output-dim index
    const int sb   = j * IN_DIM;

    // per-interval cubic polynomial table, fp16-packed, TRANSPOSED:
    // ctabh[qc][i]; word offset = qc*256 + 2i, 256 % 32 == 0 -> bank depends on
    // i only ->每 16-lane LDS.64 phase tiles all 32 banks regardless of qc.
    __shared__ uint2 ctabh[13][128];

    {
        // one thread per element row
        const int i = threadIdx.x;
        const float4 c0 = *(const float4*)&coef[(size_t)(sb + i) * 8 + 0];
        const float4 c1 = *(const float4*)&coef[(size_t)(sb + i) * 8 + 4];
        float cm[8] = {c0.x, c0.y, c0.z, c0.w, c1.x, c1.y, c1.z, c1.w};

        ctabh[0][i]  = make_uint2(0u, 0u);
        ctabh[12][i] = make_uint2(0u, 0u);
        #pragma unroll
        for (int q = 0; q < 11; q++) {
            const int m0 = q - 3;
            float k0 = (m0 + 0 >= 0 && m0 + 0 <= 7) ? cm[m0 + 0] : 0.0f;
            float k1 = (m0 + 1 >= 0 && m0 + 1 <= 7) ? cm[m0 + 1] : 0.0f;
            float k2 = (m0 + 2 >= 0 && m0 + 2 <= 7) ? cm[m0 + 2] : 0.0f;
            float k3 = (m0 + 3 >= 0 && m0 + 3 <= 7) ? cm[m0 + 3] : 0.0f;
            float A  = (k0 + 4.0f * k1 + k2) * (1.0f / 6.0f);
            float Bc = (k2 - k0) * 0.5f;
            float Cc = (k0 - 2.0f * k1 + k2) * 0.5f;
            float D  = (k3 - k0) * (1.0f / 6.0f) + (k1 - k2) * 0.5f;
            __half2 ab = __floats2half2_rn(A, Bc);
            __half2 cd = __floats2half2_rn(Cc, D);
            ctabh[q + 1][i] = make_uint2(*(unsigned*)&ab, *(unsigned*)&cd);
        }
    }

    // per-element loop-invariant setup; element r of this thread is i = lane + 32r
    float poff[4], invh[4], msb[4], mssp[4];
    #pragma unroll
    for (int r = 0; r < 4; r++) {
        const int s = sb + lane + 32 * r;
        float g0 = grid[s * 6 + 0];
        float g5 = grid[s * 6 + 5];
        float h  = (g5 - g0) * 0.2f;
        float e0 = g0 - h; e0 -= h; e0 -= h;    // match reference's sequential extension
        float ih = 1.0f / h;
        invh[r] = ih;
        poff[r] = -e0 * ih;                      // pos = t*ih + poff
        float mv = mask[s];
        msb[r]  = mv * scale_base[s];
        mssp[r] = mv * scale_sp[s];
    }

    __syncthreads();   // ctabh ready; the ONLY block barrier

    const int b_start = blockIdx.y * (4 * BB) + warp * BB;

    // hoisted, pointer-bumped addressing: stores become STG [ptr + imm]
    const size_t obase = ((size_t)b_start * OUT_DIM + j) * IN_DIM + lane;
    const float* xp  = x + (size_t)b_start * IN_DIM + lane;
    float* yo  = out + (size_t)b_start * OUT_DIM + j;
    float* pre = out + 131072            + obase;
    float* pac = out + 131072 + 16777216 + obase;
    float* psp = out + 131072 + 33554432 + obase;
    const int OSTRIDE = OUT_DIM * IN_DIM;   // 16384 floats per batch step

    float tn[4];
    #pragma unroll
    for (int r = 0; r < 4; r++) tn[r] = xp[32 * r];   // prefetch
    xp += IN_DIM;

    #pragma unroll 2
    for (int bb = 0; bb < BB; bb++) {
        float t[4];
        #pragma unroll
        for (int r = 0; r < 4; r++) t[r] = tn[r];
        if (bb + 1 < BB) {
            #pragma unroll
            for (int r = 0; r < 4; r++) tn[r] = xp[32 * r];
            xp += IN_DIM;
        }

        float y[4], spl[4];
        #pragma unroll
        for (int r = 0; r < 4; r++) {
            const int i = lane + 32 * r;

            // silu(t) = h + h*tanh(h), h = t/2  -> single MUFU.TANH (sm_75+)
            float ht = 0.5f * t[r];
            float th;
            asm("tanh.approx.f32 %0, %1;" : "=f"(th) : "f"(ht));
            float base = fmaf(ht, th, ht);

            // spline via per-interval cubic (Horner), fp16 table
            float pos = fmaf(t[r], invh[r], poff[r]);
            float qf  = floorf(pos);
            float u   = pos - qf;
            // clamp in float then one round-to-neg-inf convert; rows at the
            // clamped ends are zero so a garbage u multiplies zeros.
            int qc = __float2int_rd(fminf(fmaxf(pos, -1.0f), 11.0f)) + 1;  // 0..12

            const uint2 e = ctabh[qc][i];
            float2 ab = __half22float2(*(const __half2*)&e.x);
            float2 cd = __half22float2(*(const __half2*)&e.y);
            float sp = fmaf(fmaf(fmaf(cd.y, u, cd.x), u, ab.y), u, ab.x);

            spl[r] = sp;
            y[r]   = fmaf(msb[r], base, mssp[r] * sp);
        }

        #pragma unroll
        for (int r = 0; r < 4; r++) {
            __stcs(pre + 32 * r, t[r]);
            __stcs(pac + 32 * r, y[r]);
            __stcs(psp + 32 * r, spl[r]);
        }
        pre += OSTRIDE; pac += OSTRIDE; psp += OSTRIDE;

        // y_out[b, j] = sum over all 128 i — pure warp reduction
        float v = (y[0] + y[1]) + (y[2] + y[3]);
        #pragma unroll
        for (int o = 16; o; o >>= 1) v += __shfl_xor_sync(0xffffffffu, v, o);
        if (lane == 0) *yo = v;
        yo += OUT_DIM;
    }
}

extern "C" void kernel_launch(void* const* d_in, const int* in_sizes, int n_in,
                              void* d_out, int out_size) {
    const float* x          = (const float*)d_in[0];
    const float* grid       = (const float*)d_in[1];
    const float* coef       = (const float*)d_in[2];
    const float* scale_base = (const float*)d_in[3];
    const float* scale_sp   = (const float*)d_in[4];
    const float* mask       = (const float*)d_in[5];
    float* out = (float*)d_out;

    dim3 gridDim(OUT_DIM, BATCH / (4 * BB));   // (128, 32) = 4096 blocks
    dim3 blockDim(128);
    kan_kernel<<<gridDim, blockDim>>>(x, grid, coef, scale_base, scale_sp, mask, out);
}